// round 1
// baseline (speedup 1.0000x reference)
#include <cuda_runtime.h>
#include <cuda_bf16.h>

// Problem constants (GATLayer): V=100000, E=1600000, Fin=128, H=4, Cout=32
#define FIN   128
#define HC    128   // H*Cout
#define NHEAD 4
#define MAXV  100000
#define MAXE  1600000

// -------- scratch (static device globals; allocation-free rule) --------
__device__ __align__(16) float g_z[MAXV * HC];        // 51.2 MB
__device__ __align__(16) float g_ssrc[MAXV * NHEAD];
__device__ __align__(16) float g_sdst[MAXV * NHEAD];
__device__ __align__(16) float g_max[MAXV * NHEAD];
__device__ __align__(16) float g_denom[MAXV * NHEAD];
__device__ __align__(16) int2  g_edge[MAXE];
__device__ int g_is32;

// -------- helpers --------
__device__ __forceinline__ float lrelu(float v) {
    return v >= 0.f ? v : 0.2f * v;
}

// float atomic max via ordered-int trick (valid for all finite floats)
__device__ __forceinline__ void atomicMaxF(float* addr, float v) {
    if (v >= 0.f)
        atomicMax((int*)addr, __float_as_int(v));
    else
        atomicMin((unsigned int*)addr, __float_as_uint(v));
}

__device__ __forceinline__ void red_add_v4(float* addr, float4 v) {
    asm volatile("red.global.add.v4.f32 [%0], {%1,%2,%3,%4};"
                 :: "l"(addr), "f"(v.x), "f"(v.y), "f"(v.z), "f"(v.w)
                 : "memory");
}

// ======================================================================
// Kernel 0a/0b: edge_index dtype probe.
// If data is int64 (values < 2^31), every odd 32-bit word is 0.
// If int32, odd words are real vertex indices (virtually all nonzero).
// We only scan the first min(2E, 256K) words — safe for both layouts.
// ======================================================================
__global__ void flag_reset_kernel() {
    if (threadIdx.x == 0) g_is32 = 0;
}

__global__ void detect_kernel(const unsigned int* __restrict__ w, int n_words) {
    int i = blockIdx.x * blockDim.x + threadIdx.x;
    int j = 2 * i + 1;
    if (j < n_words && w[j] != 0u) g_is32 = 1;
}

// ======================================================================
// Kernel 1: z = x @ W   (fp32 tiled SGEMM, BM=64, BK=32, thread tile 4x8)
// ======================================================================
#define BM 64
#define BK 32
__global__ void gemm_kernel(const float* __restrict__ x,
                            const float* __restrict__ W, int V) {
    __shared__ float Ws[BK][HC];        // 16 KB
    __shared__ float xs[BM][BK + 4];    // 9.2 KB (pad keeps 16B align: 36*4=144)

    int tid = threadIdx.x;
    int tx = tid & 15;     // col group: cols [tx*8, tx*8+8)
    int ty = tid >> 4;     // row group: rows [ty*4, ty*4+4)
    int row0 = blockIdx.x * BM;

    float acc[4][8];
#pragma unroll
    for (int i = 0; i < 4; i++)
#pragma unroll
        for (int j = 0; j < 8; j++) acc[i][j] = 0.f;

    for (int kb = 0; kb < FIN; kb += BK) {
        // load Ws: BK*128 floats = 1024 float4, 4 per thread (coalesced)
#pragma unroll
        for (int i = 0; i < 4; i++) {
            int f = i * 256 + tid;
            int r = f >> 5, c4 = f & 31;
            *(float4*)&Ws[r][c4 * 4] =
                *(const float4*)&W[(kb + r) * HC + c4 * 4];
        }
        // load xs: BM*BK floats = 512 float4, 2 per thread (coalesced)
#pragma unroll
        for (int i = 0; i < 2; i++) {
            int f = i * 256 + tid;
            int r = f >> 3, c4 = f & 7;
            float4 v = make_float4(0.f, 0.f, 0.f, 0.f);
            if (row0 + r < V)
                v = *(const float4*)&x[(size_t)(row0 + r) * FIN + kb + c4 * 4];
            *(float4*)&xs[r][c4 * 4] = v;
        }
        __syncthreads();

#pragma unroll
        for (int k = 0; k < BK; k++) {
            float4 w0 = *(float4*)&Ws[k][tx * 8];
            float4 w1 = *(float4*)&Ws[k][tx * 8 + 4];
#pragma unroll
            for (int i = 0; i < 4; i++) {
                float xv = xs[ty * 4 + i][k];
                acc[i][0] += xv * w0.x; acc[i][1] += xv * w0.y;
                acc[i][2] += xv * w0.z; acc[i][3] += xv * w0.w;
                acc[i][4] += xv * w1.x; acc[i][5] += xv * w1.y;
                acc[i][6] += xv * w1.z; acc[i][7] += xv * w1.w;
            }
        }
        __syncthreads();
    }

#pragma unroll
    for (int i = 0; i < 4; i++) {
        int r = row0 + ty * 4 + i;
        if (r < V) {
            float4 o0 = make_float4(acc[i][0], acc[i][1], acc[i][2], acc[i][3]);
            float4 o1 = make_float4(acc[i][4], acc[i][5], acc[i][6], acc[i][7]);
            *(float4*)&g_z[(size_t)r * HC + tx * 8]     = o0;
            *(float4*)&g_z[(size_t)r * HC + tx * 8 + 4] = o1;
        }
    }
}

// ======================================================================
// Kernel 2: per-vertex attention scores + init max/denom + zero d_out
// thread per (v, h)
// ======================================================================
__global__ void score_kernel(const float* __restrict__ a_src,
                             const float* __restrict__ a_dst,
                             float* __restrict__ out, int V) {
    int idx = blockIdx.x * blockDim.x + threadIdx.x;
    if (idx >= V * NHEAD) return;
    int v = idx >> 2, h = idx & 3;

    const float* zp = g_z + (size_t)v * HC + h * 32;
    const float* as = a_src + h * 32;
    const float* ad = a_dst + h * 32;

    float s = 0.f, d = 0.f;
#pragma unroll
    for (int q = 0; q < 8; q++) {
        float4 zv = *(const float4*)(zp + q * 4);
        float4 av = __ldg((const float4*)(as + q * 4));
        float4 dv = __ldg((const float4*)(ad + q * 4));
        s += zv.x * av.x + zv.y * av.y + zv.z * av.z + zv.w * av.w;
        d += zv.x * dv.x + zv.y * dv.y + zv.z * dv.z + zv.w * dv.w;
    }
    g_ssrc[idx]  = s;
    g_sdst[idx]  = d;
    g_max[idx]   = -1e9f;   // NEG_INIT
    g_denom[idx] = 0.f;

    float4 z4 = make_float4(0.f, 0.f, 0.f, 0.f);
    float* op = out + (size_t)v * HC + h * 32;
#pragma unroll
    for (int q = 0; q < 8; q++) *(float4*)(op + q * 4) = z4;
}

// ======================================================================
// Kernel 3: per-edge segment max (+ convert edge_index to int2)
// ======================================================================
__global__ void max_kernel(const void* __restrict__ ei, int E) {
    int e = blockIdx.x * blockDim.x + threadIdx.x;
    if (e >= E) return;
    int src, dst;
    if (g_is32) {
        const int* p = (const int*)ei;
        src = p[e]; dst = p[E + e];
    } else {
        const long long* p = (const long long*)ei;
        src = (int)p[e]; dst = (int)p[(long long)E + e];
    }
    g_edge[e] = make_int2(src, dst);

    float4 ss = *(const float4*)&g_ssrc[src * 4];
    float4 sd = *(const float4*)&g_sdst[dst * 4];
    atomicMaxF(&g_max[dst * 4 + 0], lrelu(ss.x + sd.x));
    atomicMaxF(&g_max[dst * 4 + 1], lrelu(ss.y + sd.y));
    atomicMaxF(&g_max[dst * 4 + 2], lrelu(ss.z + sd.z));
    atomicMaxF(&g_max[dst * 4 + 3], lrelu(ss.w + sd.w));
}

// ======================================================================
// Kernel 4: per-edge exp-sum into denom
// ======================================================================
__global__ void sum_kernel(int E) {
    int e = blockIdx.x * blockDim.x + threadIdx.x;
    if (e >= E) return;
    int2 ed = g_edge[e];
    float4 ss = *(const float4*)&g_ssrc[ed.x * 4];
    float4 sd = *(const float4*)&g_sdst[ed.y * 4];
    float4 mx = *(const float4*)&g_max[ed.y * 4];
    atomicAdd(&g_denom[ed.y * 4 + 0], __expf(lrelu(ss.x + sd.x) - mx.x));
    atomicAdd(&g_denom[ed.y * 4 + 1], __expf(lrelu(ss.y + sd.y) - mx.y));
    atomicAdd(&g_denom[ed.y * 4 + 2], __expf(lrelu(ss.z + sd.z) - mx.z));
    atomicAdd(&g_denom[ed.y * 4 + 3], __expf(lrelu(ss.w + sd.w) - mx.w));
}

// ======================================================================
// Kernel 5: aggregation — one warp per edge, red.v4 into d_out
// lane l covers channels [4l, 4l+4), head = l>>3
// ======================================================================
__global__ void agg_kernel(float* __restrict__ out, int E) {
    int gw = (blockIdx.x * blockDim.x + threadIdx.x) >> 5;
    int lane = threadIdx.x & 31;
    if (gw >= E) return;

    int2 ed = g_edge[gw];
    int h = lane >> 3;

    float ev = lrelu(g_ssrc[ed.x * 4 + h] + g_sdst[ed.y * 4 + h]);
    float alpha = __expf(ev - g_max[ed.y * 4 + h]) /
                  (g_denom[ed.y * 4 + h] + 1e-9f);

    float4 zv = *(const float4*)&g_z[(size_t)ed.x * HC + lane * 4];
    zv.x *= alpha; zv.y *= alpha; zv.z *= alpha; zv.w *= alpha;
    red_add_v4(&out[(size_t)ed.y * HC + lane * 4], zv);
}

// ======================================================================
// Kernel 6: ELU epilogue in-place
// ======================================================================
__global__ void elu_kernel(float* __restrict__ out, int n4) {
    int i = blockIdx.x * blockDim.x + threadIdx.x;
    if (i >= n4) return;
    float4* p = (float4*)out;
    float4 a = p[i];
    a.x = a.x > 0.f ? a.x : expm1f(a.x);
    a.y = a.y > 0.f ? a.y : expm1f(a.y);
    a.z = a.z > 0.f ? a.z : expm1f(a.z);
    a.w = a.w > 0.f ? a.w : expm1f(a.w);
    p[i] = a;
}

// ======================================================================
extern "C" void kernel_launch(void* const* d_in, const int* in_sizes, int n_in,
                              void* d_out, int out_size) {
    const float* x     = (const float*)d_in[0];
    const void*  ei    = d_in[1];
    const float* W     = (const float*)d_in[2];
    const float* a_src = (const float*)d_in[3];
    const float* a_dst = (const float*)d_in[4];
    float* out = (float*)d_out;

    int V = in_sizes[0] / FIN;
    int E = in_sizes[1] / 2;

    // dtype probe for edge_index (int32 vs int64)
    flag_reset_kernel<<<1, 32>>>();
    int scan_words = 2 * E;
    if (scan_words > 262144) scan_words = 262144;
    int probe_threads = scan_words / 2;
    detect_kernel<<<(probe_threads + 255) / 256, 256>>>(
        (const unsigned int*)ei, scan_words);

    gemm_kernel<<<(V + BM - 1) / BM, 256>>>(x, W, V);
    score_kernel<<<(V * NHEAD + 255) / 256, 256>>>(a_src, a_dst, out, V);
    max_kernel<<<(E + 255) / 256, 256>>>(ei, E);
    sum_kernel<<<(E + 255) / 256, 256>>>(E);
    agg_kernel<<<(E + 7) / 8, 256>>>(out, E);   // 8 warps/block, warp per edge
    elu_kernel<<<(V * (HC / 4) + 255) / 256, 256>>>(out, V * (HC / 4));
}